// round 1
// baseline (speedup 1.0000x reference)
#include <cuda_runtime.h>

// Problem shape (fixed by the reference): B=2, H=16, S=2048, D=128, fp32.
constexpr int Bc = 2, Hc = 16, Sc = 2048, Dc = 128;
constexpr int BM = 128;       // q rows per CTA
constexpr int BN = 128;       // kv cols per tile
constexpr int NTHREADS = 256; // 16x16 thread grid, 8x8 micro-tile each

// Shared memory: Qs [BM][Dc] + Xs (Kt [Dc][BN] then Ps [BM][BN]) + Vs [BN][Dc]
// = 3 * 64KB = 192KB dynamic smem, 1 CTA/SM.
constexpr int SMEM_BYTES = 3 * BM * Dc * (int)sizeof(float);

__global__ __launch_bounds__(NTHREADS, 1)
void attn128(const float* __restrict__ Q, const float* __restrict__ K,
             const float* __restrict__ V, const float* __restrict__ AM,
             const float* __restrict__ HM, const float* __restrict__ CTX,
             float* __restrict__ O)
{
    extern __shared__ float sm[];
    float* Qs = sm;               // [BM][Dc] row-major (m, d)
    float* Xs = sm + BM * Dc;     // phase 1: K^T [d][n]; phase 2: P [m][kv]
    float* Vs = sm + 2 * BM * Dc; // [kv][d] row-major

    const int tid = threadIdx.x;
    const int tx  = tid & 15;     // covers 8 kv-cols (QK) / 8 d-cols (PV, out)
    const int ty  = tid >> 4;     // covers 8 q-rows
    const int qi  = blockIdx.x;   // q tile index
    const int bh  = blockIdx.y;   // b*H + h
    const int b   = bh >> 4;
    const int h   = bh & 15;
    const int q0  = qi * BM;

    const float* Qg = Q + ((size_t)bh * Sc + q0) * Dc;

    float acc[8][8];
    float m_i[8], l_i[8];
    #pragma unroll
    for (int i = 0; i < 8; i++) {
        m_i[i] = -1e30f;
        l_i[i] = 0.f;
        #pragma unroll
        for (int n = 0; n < 8; n++) acc[i][n] = 0.f;
    }

    // ---- stage Q tile (coalesced float4, conflict-free STS) ----
    #pragma unroll 1
    for (int t = tid; t < BM * (Dc / 4); t += NTHREADS) {
        int r = t >> 5;            // row 0..127
        int c = (t & 31) << 2;     // d 0..124 step 4
        *(float4*)&Qs[r * Dc + c] = *(const float4*)&Qg[r * Dc + c];
    }

    // ---- kv tiles (causal: only j <= qi) ----
    for (int j = 0; j <= qi; j++) {
        const int kv0 = j * BN;
        const float* Kg = K + ((size_t)bh * Sc + kv0) * Dc;
        const float* Vg = V + ((size_t)bh * Sc + kv0) * Dc;

        __syncthreads();  // prior PV done reading Xs/Vs (and Qs staged, iter 0)

        // K staged transposed: Xs[d][n]. Per warp: one d-chunk (16B) x 32 rows,
        // scalar STS to consecutive n => consecutive banks, conflict-free.
        #pragma unroll 1
        for (int t = tid; t < BN * (Dc / 4); t += NTHREADS) {
            int n  = t & 127;      // kv row
            int c4 = t >> 7;       // d chunk 0..31
            float4 kk = *(const float4*)&Kg[n * Dc + (c4 << 2)];
            int d0 = c4 << 2;
            Xs[(d0 + 0) * BN + n] = kk.x;
            Xs[(d0 + 1) * BN + n] = kk.y;
            Xs[(d0 + 2) * BN + n] = kk.z;
            Xs[(d0 + 3) * BN + n] = kk.w;
        }
        // V staged row-major (direct copy)
        #pragma unroll 1
        for (int t = tid; t < BN * (Dc / 4); t += NTHREADS) {
            int r = t >> 5;
            int c = (t & 31) << 2;
            *(float4*)&Vs[r * Dc + c] = *(const float4*)&Vg[r * Dc + c];
        }
        __syncthreads();

        // ---- S = Q K^T (raw logits, NO 1/sqrt(d) per reference) ----
        float s[8][8];
        #pragma unroll
        for (int i = 0; i < 8; i++)
            #pragma unroll
            for (int n = 0; n < 8; n++) s[i][n] = 0.f;

        #pragma unroll 2
        for (int d4 = 0; d4 < Dc; d4 += 4) {
            float4 a[8];
            #pragma unroll
            for (int i = 0; i < 8; i++)
                a[i] = *(const float4*)&Qs[(ty * 8 + i) * Dc + d4];
            #pragma unroll
            for (int dd = 0; dd < 4; dd++) {
                float4 b0 = *(const float4*)&Xs[(d4 + dd) * BN + tx * 8];
                float4 b1 = *(const float4*)&Xs[(d4 + dd) * BN + tx * 8 + 4];
                float bv[8] = {b0.x, b0.y, b0.z, b0.w, b1.x, b1.y, b1.z, b1.w};
                #pragma unroll
                for (int i = 0; i < 8; i++) {
                    float av = (dd == 0) ? a[i].x : (dd == 1) ? a[i].y
                             : (dd == 2) ? a[i].z : a[i].w;
                    #pragma unroll
                    for (int n = 0; n < 8; n++)
                        s[i][n] += av * bv[n];
                }
            }
        }

        // ---- masks ----
        float am[8], cx[8];
        #pragma unroll
        for (int n = 0; n < 8; n++) {
            am[n] = AM[b * Sc + kv0 + tx * 8 + n];   // additive attention_mask
            cx[n] = CTX[b * Sc + kv0 + tx * 8 + n];  // post-softmax ctx scale
        }
        #pragma unroll
        for (int i = 0; i < 8; i++)
            #pragma unroll
            for (int n = 0; n < 8; n++)
                s[i][n] += am[n];
        if (j == qi) {  // diagonal tile: causal mask (kv > q)
            #pragma unroll
            for (int i = 0; i < 8; i++) {
                int ri = ty * 8 + i;
                #pragma unroll
                for (int n = 0; n < 8; n++)
                    if (tx * 8 + n > ri) s[i][n] = -1e30f;
            }
        }

        // ---- online softmax (row stats across 16 lanes sharing a row) ----
        #pragma unroll
        for (int i = 0; i < 8; i++) {
            float mx = s[i][0];
            #pragma unroll
            for (int n = 1; n < 8; n++) mx = fmaxf(mx, s[i][n]);
            #pragma unroll
            for (int w = 8; w >= 1; w >>= 1)
                mx = fmaxf(mx, __shfl_xor_sync(0xffffffffu, mx, w));
            float mnew = fmaxf(m_i[i], mx);
            float corr = __expf(m_i[i] - mnew);
            float ls = 0.f;
            #pragma unroll
            for (int n = 0; n < 8; n++) {
                float p = __expf(s[i][n] - mnew);
                s[i][n] = p;
                ls += p;
            }
            #pragma unroll
            for (int w = 8; w >= 1; w >>= 1)
                ls += __shfl_xor_sync(0xffffffffu, ls, w);
            l_i[i] = l_i[i] * corr + ls;   // normalizer: WITHOUT ctx (post-softmax)
            m_i[i] = mnew;
            #pragma unroll
            for (int n = 0; n < 8; n++) acc[i][n] *= corr;
        }

        // ---- write P (with ctx folded in) into Xs, reuse as [m][kv] ----
        __syncthreads();  // everyone done reading Kt from Xs
        #pragma unroll
        for (int i = 0; i < 8; i++) {
            float4 p0 = make_float4(s[i][0] * cx[0], s[i][1] * cx[1],
                                    s[i][2] * cx[2], s[i][3] * cx[3]);
            float4 p1 = make_float4(s[i][4] * cx[4], s[i][5] * cx[5],
                                    s[i][6] * cx[6], s[i][7] * cx[7]);
            *(float4*)&Xs[(ty * 8 + i) * BN + tx * 8]     = p0;
            *(float4*)&Xs[(ty * 8 + i) * BN + tx * 8 + 4] = p1;
        }
        __syncthreads();

        // ---- O += P V ----
        #pragma unroll 2
        for (int k4 = 0; k4 < BN; k4 += 4) {
            float4 a[8];
            #pragma unroll
            for (int i = 0; i < 8; i++)
                a[i] = *(const float4*)&Xs[(ty * 8 + i) * BN + k4];
            #pragma unroll
            for (int kk = 0; kk < 4; kk++) {
                float4 b0 = *(const float4*)&Vs[(k4 + kk) * Dc + tx * 8];
                float4 b1 = *(const float4*)&Vs[(k4 + kk) * Dc + tx * 8 + 4];
                float bv[8] = {b0.x, b0.y, b0.z, b0.w, b1.x, b1.y, b1.z, b1.w};
                #pragma unroll
                for (int i = 0; i < 8; i++) {
                    float av = (kk == 0) ? a[i].x : (kk == 1) ? a[i].y
                             : (kk == 2) ? a[i].z : a[i].w;
                    #pragma unroll
                    for (int n = 0; n < 8; n++)
                        acc[i][n] += av * bv[n];
                }
            }
        }
    }

    // ---- epilogue: /l, *head_mask, store ----
    const float hm = HM[h];
    #pragma unroll
    for (int i = 0; i < 8; i++) {
        float inv = hm / l_i[i];
        float* Og = O + ((size_t)bh * Sc + (q0 + ty * 8 + i)) * Dc + tx * 8;
        float4 o0 = make_float4(acc[i][0] * inv, acc[i][1] * inv,
                                acc[i][2] * inv, acc[i][3] * inv);
        float4 o1 = make_float4(acc[i][4] * inv, acc[i][5] * inv,
                                acc[i][6] * inv, acc[i][7] * inv);
        *(float4*)&Og[0] = o0;
        *(float4*)&Og[4] = o1;
    }
}

extern "C" void kernel_launch(void* const* d_in, const int* in_sizes, int n_in,
                              void* d_out, int out_size)
{
    const float* q   = (const float*)d_in[0];
    const float* k   = (const float*)d_in[1];
    const float* v   = (const float*)d_in[2];
    const float* am  = (const float*)d_in[3];  // [B,1,1,S]
    const float* hm  = (const float*)d_in[4];  // [1,H,1,1]
    const float* ctx = (const float*)d_in[5];  // [B,S]
    float* out = (float*)d_out;                // [B,H,S,D] fp32

    // Idempotent, deterministic, not a stream op (graph-capture safe).
    cudaFuncSetAttribute(attn128, cudaFuncAttributeMaxDynamicSharedMemorySize,
                         SMEM_BYTES);
    attn128<<<dim3(Sc / BM, Bc * Hc), NTHREADS, SMEM_BYTES>>>(
        q, k, v, am, hm, ctx, out);
}

// round 3
// speedup vs baseline: 1.4553x; 1.4553x over previous
#include <cuda_runtime.h>
#include <cuda_bf16.h>
#include <cstdint>

// Shape: B=2, H=16, S=2048, D=128, fp32 in/out. GPT-Neo attention, no 1/sqrt(d).
constexpr int Sc = 2048, Dc = 128, NTH = 256;
constexpr int ROWE = 136;                 // bf16 elems per padded row (128 + 8)
constexpr int TILE_E = 128 * ROWE;        // elems per 128x128 tile
constexpr int HDR_B = 1024;               // AM/CX header bytes
constexpr int SMEM_BYTES = HDR_B + 6 * TILE_E * 2;   // ~205 KB

__device__ __forceinline__ uint32_t smem_u32(const void* p) {
    uint32_t a;
    asm("{ .reg .u64 t; cvta.to.shared.u64 t, %1; cvt.u32.u64 %0, t; }"
        : "=r"(a) : "l"(p));
    return a;
}
__device__ __forceinline__ void ldsm4(uint32_t* r, uint32_t a) {
    asm volatile("ldmatrix.sync.aligned.m8n8.x4.shared.b16 {%0,%1,%2,%3}, [%4];"
                 : "=r"(r[0]), "=r"(r[1]), "=r"(r[2]), "=r"(r[3]) : "r"(a));
}
__device__ __forceinline__ void ldsm4t(uint32_t* r, uint32_t a) {
    asm volatile("ldmatrix.sync.aligned.m8n8.x4.trans.shared.b16 {%0,%1,%2,%3}, [%4];"
                 : "=r"(r[0]), "=r"(r[1]), "=r"(r[2]), "=r"(r[3]) : "r"(a));
}
__device__ __forceinline__ void mma16816(float* d, const uint32_t* a, const uint32_t* b) {
    asm volatile("mma.sync.aligned.m16n8k16.row.col.f32.bf16.bf16.f32 "
                 "{%0,%1,%2,%3}, {%4,%5,%6,%7}, {%8,%9}, {%0,%1,%2,%3};"
                 : "+f"(d[0]), "+f"(d[1]), "+f"(d[2]), "+f"(d[3])
                 : "r"(a[0]), "r"(a[1]), "r"(a[2]), "r"(a[3]), "r"(b[0]), "r"(b[1]));
}
__device__ __forceinline__ uint32_t packbf(__nv_bfloat16 lo, __nv_bfloat16 hi) {
    __nv_bfloat162 v(lo, hi);   // .x -> low 16 bits
    return *(uint32_t*)&v;
}

// Stage a [128 x 128] fp32 row-major tile as hi/lo bf16 padded row-major tiles.
__device__ __forceinline__ void stage_rm(const float* __restrict__ g,
                                         __nv_bfloat16* hi, __nv_bfloat16* lo, int tid) {
    #pragma unroll 1
    for (int t = tid; t < 128 * 32; t += NTH) {
        int r = t >> 5, c4 = (t & 31) << 2;
        float4 x = *(const float4*)&g[r * Dc + c4];
        __nv_bfloat16 h0 = __float2bfloat16(x.x), h1 = __float2bfloat16(x.y);
        __nv_bfloat16 h2 = __float2bfloat16(x.z), h3 = __float2bfloat16(x.w);
        __nv_bfloat16 l0 = __float2bfloat16(x.x - __bfloat162float(h0));
        __nv_bfloat16 l1 = __float2bfloat16(x.y - __bfloat162float(h1));
        __nv_bfloat16 l2 = __float2bfloat16(x.z - __bfloat162float(h2));
        __nv_bfloat16 l3 = __float2bfloat16(x.w - __bfloat162float(h3));
        int e = r * ROWE + c4;
        *(uint2*)&hi[e] = make_uint2(packbf(h0, h1), packbf(h2, h3));
        *(uint2*)&lo[e] = make_uint2(packbf(l0, l1), packbf(l2, l3));
    }
}

__global__ __launch_bounds__(NTH, 1)
void attn_hmma(const float* __restrict__ Q, const float* __restrict__ K,
               const float* __restrict__ V, const float* __restrict__ AM,
               const float* __restrict__ HM, const float* __restrict__ CTX,
               float* __restrict__ O)
{
    extern __shared__ char sm[];
    float* AMs = (float*)sm;
    float* CXs = AMs + 128;
    __nv_bfloat16* bfr = (__nv_bfloat16*)(sm + HDR_B);
    __nv_bfloat16* QHI = bfr;
    __nv_bfloat16* QLO = bfr + TILE_E;
    __nv_bfloat16* KHI = bfr + 2 * TILE_E;
    __nv_bfloat16* KLO = bfr + 3 * TILE_E;
    __nv_bfloat16* VHI = bfr + 4 * TILE_E;
    __nv_bfloat16* VLO = bfr + 5 * TILE_E;

    const uint32_t sb = smem_u32(sm);
    const uint32_t uQHI = sb + HDR_B;
    const uint32_t uQLO = uQHI + TILE_E * 2;
    const uint32_t uKHI = uQLO + TILE_E * 2;
    const uint32_t uKLO = uKHI + TILE_E * 2;
    const uint32_t uVHI = uKLO + TILE_E * 2;
    const uint32_t uVLO = uVHI + TILE_E * 2;

    const int tid = threadIdx.x, lane = tid & 31, warp = tid >> 5;
    const int wrow = warp * 16;               // first q-row of this warp
    const int qi = blockIdx.x, bh = blockIdx.y, b = bh >> 4, h = bh & 15;
    const int q0 = qi * 128;

    // ldmatrix lane->address components (element offsets)
    // A (Q, non-trans): row = wrow + (lane&15), col half = (lane>>4)*8
    const uint32_t aoffA = (uint32_t)((wrow + (lane & 15)) * ROWE + (lane >> 4) * 8) * 2;
    // B (K, non-trans): nrow = (lane&7) + (lane>=16 ? 8:0), kcol half = ((lane>>3)&1)*8
    const uint32_t aoffB = (uint32_t)(((lane & 7) + ((lane >> 4) << 3)) * ROWE
                                      + (((lane >> 3) & 1) << 3)) * 2;
    // B (V, trans): krow = (lane&7) + ((lane>>3)&1)*8, ncol half = (lane>=16 ? 8:0)
    const uint32_t aoffBT = (uint32_t)(((lane & 7) + (((lane >> 3) & 1) << 3)) * ROWE
                                       + ((lane >> 4) << 3)) * 2;

    // accumulators / state
    float o[64];                              // O frag: 16 d-tiles x 4
    #pragma unroll
    for (int i = 0; i < 64; i++) o[i] = 0.f;
    float m0 = -1e30f, m1 = -1e30f, l0 = 0.f, l1 = 0.f;

    // stage Q hi/lo once (visible after first __syncthreads in loop)
    stage_rm(Q + ((size_t)bh * Sc + q0) * Dc, QHI, QLO, tid);

    for (int j = 0; j <= qi; j++) {
        const int kv0 = j * 128;
        __syncthreads();   // smem reuse safe; also publishes Q on iter 0
        // stage AM/CX (256 floats) + K + V
        if (tid < 64) {
            const float* src = (tid < 32) ? (AM + b * Sc + kv0) : (CTX + b * Sc + kv0);
            float* dst = (tid < 32) ? AMs : CXs;
            int t = (tid & 31) << 2;
            *(float4*)&dst[t] = *(const float4*)&src[t];
        }
        stage_rm(K + ((size_t)bh * Sc + kv0) * Dc, KHI, KLO, tid);
        stage_rm(V + ((size_t)bh * Sc + kv0) * Dc, VHI, VLO, tid);
        __syncthreads();

        // ================= S = Q K^T (3 split passes fused) =================
        float s[64];
        #pragma unroll
        for (int i = 0; i < 64; i++) s[i] = 0.f;

        #pragma unroll 1
        for (int ks = 0; ks < 8; ks++) {
            uint32_t ah[4], al[4];
            ldsm4(ah, uQHI + aoffA + ks * 32);
            ldsm4(al, uQLO + aoffA + ks * 32);
            #pragma unroll
            for (int np = 0; np < 8; np++) {
                uint32_t bh4[4], bl4[4];
                uint32_t bo = aoffB + (uint32_t)(np * 16 * ROWE) * 2 + ks * 32;
                ldsm4(bh4, uKHI + bo);
                ldsm4(bl4, uKLO + bo);
                mma16816(&s[(2 * np) * 4],     ah, bh4);
                mma16816(&s[(2 * np + 1) * 4], ah, bh4 + 2);
                mma16816(&s[(2 * np) * 4],     ah, bl4);
                mma16816(&s[(2 * np + 1) * 4], ah, bl4 + 2);
                mma16816(&s[(2 * np) * 4],     al, bh4);
                mma16816(&s[(2 * np + 1) * 4], al, bh4 + 2);
            }
        }

        // ================= masks + online softmax (warp-local) ==============
        #pragma unroll
        for (int t = 0; t < 16; t++) {
            float2 a2 = *(const float2*)&AMs[t * 8 + (lane & 3) * 2];
            s[t * 4 + 0] += a2.x; s[t * 4 + 1] += a2.y;
            s[t * 4 + 2] += a2.x; s[t * 4 + 3] += a2.y;
        }
        if (j == qi) {
            const int wr0 = wrow + (lane >> 2), wr1 = wr0 + 8;
            #pragma unroll
            for (int t = 0; t < 16; t++) {
                int c0 = t * 8 + (lane & 3) * 2;
                if (c0     > wr0) s[t * 4 + 0] = -1e30f;
                if (c0 + 1 > wr0) s[t * 4 + 1] = -1e30f;
                if (c0     > wr1) s[t * 4 + 2] = -1e30f;
                if (c0 + 1 > wr1) s[t * 4 + 3] = -1e30f;
            }
        }
        float mx0 = -1e30f, mx1 = -1e30f;
        #pragma unroll
        for (int t = 0; t < 16; t++) {
            mx0 = fmaxf(mx0, fmaxf(s[t * 4 + 0], s[t * 4 + 1]));
            mx1 = fmaxf(mx1, fmaxf(s[t * 4 + 2], s[t * 4 + 3]));
        }
        mx0 = fmaxf(mx0, __shfl_xor_sync(0xffffffffu, mx0, 1));
        mx0 = fmaxf(mx0, __shfl_xor_sync(0xffffffffu, mx0, 2));
        mx1 = fmaxf(mx1, __shfl_xor_sync(0xffffffffu, mx1, 1));
        mx1 = fmaxf(mx1, __shfl_xor_sync(0xffffffffu, mx1, 2));
        const float mn0 = fmaxf(m0, mx0), mn1 = fmaxf(m1, mx1);
        const float corr0 = __expf(m0 - mn0), corr1 = __expf(m1 - mn1);

        uint32_t ph0[16], ph1[16], pl0[16], pl1[16];
        float ls0 = 0.f, ls1 = 0.f;
        #pragma unroll
        for (int t = 0; t < 16; t++) {
            float p0 = __expf(s[t * 4 + 0] - mn0);
            float p1 = __expf(s[t * 4 + 1] - mn0);
            float p2 = __expf(s[t * 4 + 2] - mn1);
            float p3 = __expf(s[t * 4 + 3] - mn1);
            ls0 += p0 + p1; ls1 += p2 + p3;
            float2 cx = *(const float2*)&CXs[t * 8 + (lane & 3) * 2];
            p0 *= cx.x; p1 *= cx.y; p2 *= cx.x; p3 *= cx.y;
            __nv_bfloat16 h0 = __float2bfloat16(p0), h1 = __float2bfloat16(p1);
            __nv_bfloat16 h2 = __float2bfloat16(p2), h3 = __float2bfloat16(p3);
            ph0[t] = packbf(h0, h1);
            ph1[t] = packbf(h2, h3);
            pl0[t] = packbf(__float2bfloat16(p0 - __bfloat162float(h0)),
                            __float2bfloat16(p1 - __bfloat162float(h1)));
            pl1[t] = packbf(__float2bfloat16(p2 - __bfloat162float(h2)),
                            __float2bfloat16(p3 - __bfloat162float(h3)));
        }
        ls0 += __shfl_xor_sync(0xffffffffu, ls0, 1);
        ls0 += __shfl_xor_sync(0xffffffffu, ls0, 2);
        ls1 += __shfl_xor_sync(0xffffffffu, ls1, 1);
        ls1 += __shfl_xor_sync(0xffffffffu, ls1, 2);
        l0 = l0 * corr0 + ls0;  m0 = mn0;
        l1 = l1 * corr1 + ls1;  m1 = mn1;
        #pragma unroll
        for (int t = 0; t < 16; t++) {
            o[t * 4 + 0] *= corr0; o[t * 4 + 1] *= corr0;
            o[t * 4 + 2] *= corr1; o[t * 4 + 3] *= corr1;
        }

        // ================= O += P V (3 split passes fused) ==================
        #pragma unroll 1
        for (int ks = 0; ks < 8; ks++) {
            uint32_t afh[4] = {ph0[2 * ks], ph1[2 * ks], ph0[2 * ks + 1], ph1[2 * ks + 1]};
            uint32_t afl[4] = {pl0[2 * ks], pl1[2 * ks], pl0[2 * ks + 1], pl1[2 * ks + 1]};
            #pragma unroll
            for (int dp = 0; dp < 8; dp++) {
                uint32_t bvh[4], bvl[4];
                uint32_t bo = aoffBT + (uint32_t)(ks * 16 * ROWE) * 2 + dp * 32;
                ldsm4t(bvh, uVHI + bo);
                ldsm4t(bvl, uVLO + bo);
                mma16816(&o[(2 * dp) * 4],     afh, bvh);
                mma16816(&o[(2 * dp + 1) * 4], afh, bvh + 2);
                mma16816(&o[(2 * dp) * 4],     afh, bvl);
                mma16816(&o[(2 * dp + 1) * 4], afh, bvl + 2);
                mma16816(&o[(2 * dp) * 4],     afl, bvh);
                mma16816(&o[(2 * dp + 1) * 4], afl, bvh + 2);
            }
        }
    }

    // ================= epilogue =================
    const float hm = HM[h];
    const float sc0 = hm / l0, sc1 = hm / l1;
    const int gr0 = q0 + wrow + (lane >> 2);
    float* O0 = O + ((size_t)bh * Sc + gr0) * Dc;
    float* O1 = O0 + 8 * Dc;
    #pragma unroll
    for (int t = 0; t < 16; t++) {
        int c0 = t * 8 + (lane & 3) * 2;
        *(float2*)&O0[c0] = make_float2(o[t * 4 + 0] * sc0, o[t * 4 + 1] * sc0);
        *(float2*)&O1[c0] = make_float2(o[t * 4 + 2] * sc1, o[t * 4 + 3] * sc1);
    }
}

extern "C" void kernel_launch(void* const* d_in, const int* in_sizes, int n_in,
                              void* d_out, int out_size)
{
    const float* q   = (const float*)d_in[0];
    const float* k   = (const float*)d_in[1];
    const float* v   = (const float*)d_in[2];
    const float* am  = (const float*)d_in[3];
    const float* hm  = (const float*)d_in[4];
    const float* ctx = (const float*)d_in[5];
    float* out = (float*)d_out;

    cudaFuncSetAttribute(attn_hmma, cudaFuncAttributeMaxDynamicSharedMemorySize,
                         SMEM_BYTES);
    attn_hmma<<<dim3(Sc / 128, 32), NTH, SMEM_BYTES>>>(q, k, v, am, hm, ctx, out);
}

// round 4
// speedup vs baseline: 3.6488x; 2.5072x over previous
#include <cuda_runtime.h>
#include <cuda_bf16.h>
#include <cstdint>

// Shape: B=2, H=16, S=2048, D=128, fp32 in/out. GPT-Neo attention, no 1/sqrt(d).
constexpr int Sc = 2048, Dc = 128, NTH = 256;
constexpr int ROWE = 136;                   // bf16 elems per padded smem row
constexpr int BHSD = 2 * 16 * 2048 * 128;   // 8388608

// Preconverted hi/lo bf16 copies of Q, K, V (device scratch; no runtime alloc).
__device__ __align__(16) __nv_bfloat16 g_qhi[BHSD];
__device__ __align__(16) __nv_bfloat16 g_qlo[BHSD];
__device__ __align__(16) __nv_bfloat16 g_khi[BHSD];
__device__ __align__(16) __nv_bfloat16 g_klo[BHSD];
__device__ __align__(16) __nv_bfloat16 g_vhi[BHSD];
__device__ __align__(16) __nv_bfloat16 g_vlo[BHSD];

// ---- smem layout (bytes) ----
constexpr int OFF_AM = 0;                   // float[2048]
constexpr int OFF_CX = 8192;                // float[2048]
constexpr int TILE_B = 128 * ROWE * 2;      // 34816 B per bf16 tile
constexpr int OFF_QHI = 16384;
constexpr int OFF_QLO = OFF_QHI + TILE_B;
constexpr int OFF_KHI = OFF_QLO + TILE_B;
constexpr int OFF_KLO = OFF_KHI + TILE_B;
constexpr int OFF_VHI = OFF_KLO + TILE_B;
constexpr int OFF_VLO = OFF_VHI + TILE_B;
constexpr int SMEM_BYTES = OFF_VLO + TILE_B;        // 225280 B

__device__ __forceinline__ uint32_t smem_u32(const void* p) {
    uint32_t a;
    asm("{ .reg .u64 t; cvta.to.shared.u64 t, %1; cvt.u32.u64 %0, t; }"
        : "=r"(a) : "l"(p));
    return a;
}
__device__ __forceinline__ void cpa(uint32_t d, const void* s) {
    asm volatile("cp.async.cg.shared.global [%0], [%1], 16;" :: "r"(d), "l"(s));
}
#define CP_COMMIT() asm volatile("cp.async.commit_group;" ::: "memory")
#define CP_WAIT0()  asm volatile("cp.async.wait_group 0;" ::: "memory")

__device__ __forceinline__ void ldsm4(uint32_t* r, uint32_t a) {
    asm volatile("ldmatrix.sync.aligned.m8n8.x4.shared.b16 {%0,%1,%2,%3}, [%4];"
                 : "=r"(r[0]), "=r"(r[1]), "=r"(r[2]), "=r"(r[3]) : "r"(a));
}
__device__ __forceinline__ void ldsm4t(uint32_t* r, uint32_t a) {
    asm volatile("ldmatrix.sync.aligned.m8n8.x4.trans.shared.b16 {%0,%1,%2,%3}, [%4];"
                 : "=r"(r[0]), "=r"(r[1]), "=r"(r[2]), "=r"(r[3]) : "r"(a));
}
__device__ __forceinline__ void mma16816(float* d, const uint32_t* a, const uint32_t* b) {
    asm volatile("mma.sync.aligned.m16n8k16.row.col.f32.bf16.bf16.f32 "
                 "{%0,%1,%2,%3}, {%4,%5,%6,%7}, {%8,%9}, {%0,%1,%2,%3};"
                 : "+f"(d[0]), "+f"(d[1]), "+f"(d[2]), "+f"(d[3])
                 : "r"(a[0]), "r"(a[1]), "r"(a[2]), "r"(a[3]), "r"(b[0]), "r"(b[1]));
}
__device__ __forceinline__ uint32_t packbf(__nv_bfloat16 lo, __nv_bfloat16 hi) {
    __nv_bfloat162 v(lo, hi);
    return *(uint32_t*)&v;
}

// ---- preconvert: fp32 -> hi/lo bf16 (runs once per launch, pure BW) ----
__global__ __launch_bounds__(256)
void convert_split(const float* __restrict__ Q, const float* __restrict__ K,
                   const float* __restrict__ V)
{
    int t = blockIdx.x * 256 + threadIdx.x;
    int i = t * 4;
    const float* src;
    __nv_bfloat16 *hi, *lo;
    if (blockIdx.y == 0)      { src = Q; hi = g_qhi; lo = g_qlo; }
    else if (blockIdx.y == 1) { src = K; hi = g_khi; lo = g_klo; }
    else                      { src = V; hi = g_vhi; lo = g_vlo; }
    float4 x = *(const float4*)(src + i);
    __nv_bfloat16 h0 = __float2bfloat16(x.x), h1 = __float2bfloat16(x.y);
    __nv_bfloat16 h2 = __float2bfloat16(x.z), h3 = __float2bfloat16(x.w);
    __nv_bfloat16 l0 = __float2bfloat16(x.x - __bfloat162float(h0));
    __nv_bfloat16 l1 = __float2bfloat16(x.y - __bfloat162float(h1));
    __nv_bfloat16 l2 = __float2bfloat16(x.z - __bfloat162float(h2));
    __nv_bfloat16 l3 = __float2bfloat16(x.w - __bfloat162float(h3));
    *(uint2*)&hi[i] = make_uint2(packbf(h0, h1), packbf(h2, h3));
    *(uint2*)&lo[i] = make_uint2(packbf(l0, l1), packbf(l2, l3));
}

// ---- main attention kernel ----
__global__ __launch_bounds__(NTH, 1)
void attn_hmma(const float* __restrict__ AM, const float* __restrict__ HM,
               const float* __restrict__ CTX, float* __restrict__ O)
{
    extern __shared__ char sm[];
    float* AMs = (float*)(sm + OFF_AM);
    float* CXs = (float*)(sm + OFF_CX);
    const uint32_t sb = smem_u32(sm);
    const uint32_t uQHI = sb + OFF_QHI, uQLO = sb + OFF_QLO;
    const uint32_t uKHI = sb + OFF_KHI, uKLO = sb + OFF_KLO;
    const uint32_t uVHI = sb + OFF_VHI, uVLO = sb + OFF_VLO;

    const int tid = threadIdx.x, lane = tid & 31, warp = tid >> 5;
    const int wrow = warp * 16;
    // LPT order: heavy (qi=15) CTAs first
    const int bx = blockIdx.x;
    const int qi = (Sc / 128 - 1) - (bx >> 5);
    const int bh = bx & 31, b = bh >> 4, h = bh & 15;
    const int q0 = qi * 128;

    // ldmatrix lane->address offsets (bytes)
    const uint32_t aoffA = (uint32_t)((wrow + (lane & 15)) * ROWE + (lane >> 4) * 8) * 2;
    const uint32_t aoffB = (uint32_t)(((lane & 7) + ((lane >> 4) << 3)) * ROWE
                                      + (((lane >> 3) & 1) << 3)) * 2;
    const uint32_t aoffBT = (uint32_t)(((lane & 7) + (((lane >> 3) & 1) << 3)) * ROWE
                                       + ((lane >> 4) << 3)) * 2;

    float o[64];
    #pragma unroll
    for (int i = 0; i < 64; i++) o[i] = 0.f;
    float m0 = -1e30f, m1 = -1e30f, l0 = 0.f, l1 = 0.f;

    // ---- one-time staging: AM/CX rows + Q hi/lo tile (joins tile-0 group) ----
    #pragma unroll
    for (int i2 = 0; i2 < 4; i2++) {
        int id = tid + 256 * i2;                       // 0..1023
        if (id < 512) cpa(sb + OFF_AM + id * 16, (const char*)(AM + b * Sc) + id * 16);
        else cpa(sb + OFF_CX + (id - 512) * 16,
                 (const char*)(CTX + b * Sc) + (id - 512) * 16);
    }
    {
        const char* gqh = (const char*)(g_qhi + ((size_t)bh * Sc + q0) * Dc);
        const char* gql = (const char*)(g_qlo + ((size_t)bh * Sc + q0) * Dc);
        #pragma unroll
        for (int i2 = 0; i2 < 8; i2++) {
            int id = tid + 256 * i2;                   // 0..2047
            int r = id >> 4, c = id & 15;
            uint32_t so = (uint32_t)(r * (ROWE * 2) + c * 16);
            uint32_t go = (uint32_t)(r * (Dc * 2) + c * 16);
            cpa(uQHI + so, gqh + go);
            cpa(uQLO + so, gql + go);
        }
    }

    for (int j = 0; j <= qi; j++) {
        const int kv0 = j * 128;
        __syncthreads();   // previous tile's compute done reading K/V smem

        // ---- stage K/V hi/lo via cp.async (preconverted bf16) ----
        const char* gkh = (const char*)(g_khi + ((size_t)bh * Sc + kv0) * Dc);
        const char* gkl = (const char*)(g_klo + ((size_t)bh * Sc + kv0) * Dc);
        const char* gvh = (const char*)(g_vhi + ((size_t)bh * Sc + kv0) * Dc);
        const char* gvl = (const char*)(g_vlo + ((size_t)bh * Sc + kv0) * Dc);
        #pragma unroll
        for (int i2 = 0; i2 < 8; i2++) {
            int id = tid + 256 * i2;
            int r = id >> 4, c = id & 15;
            uint32_t so = (uint32_t)(r * (ROWE * 2) + c * 16);
            uint32_t go = (uint32_t)(r * (Dc * 2) + c * 16);
            cpa(uKHI + so, gkh + go);
            cpa(uKLO + so, gkl + go);
            cpa(uVHI + so, gvh + go);
            cpa(uVLO + so, gvl + go);
        }
        CP_COMMIT();
        CP_WAIT0();
        __syncthreads();

        // ================= S = Q K^T (3 split passes fused) =================
        float s[64];
        #pragma unroll
        for (int i = 0; i < 64; i++) s[i] = 0.f;

        #pragma unroll 1
        for (int ks = 0; ks < 8; ks++) {
            uint32_t ah[4], al[4];
            ldsm4(ah, uQHI + aoffA + ks * 32);
            ldsm4(al, uQLO + aoffA + ks * 32);
            #pragma unroll
            for (int np = 0; np < 8; np++) {
                uint32_t bh4[4], bl4[4];
                uint32_t bo = aoffB + (uint32_t)(np * 16 * ROWE) * 2 + ks * 32;
                ldsm4(bh4, uKHI + bo);
                ldsm4(bl4, uKLO + bo);
                mma16816(&s[(2 * np) * 4],     ah, bh4);
                mma16816(&s[(2 * np + 1) * 4], ah, bh4 + 2);
                mma16816(&s[(2 * np) * 4],     ah, bl4);
                mma16816(&s[(2 * np + 1) * 4], ah, bl4 + 2);
                mma16816(&s[(2 * np) * 4],     al, bh4);
                mma16816(&s[(2 * np + 1) * 4], al, bh4 + 2);
            }
        }

        // ================= masks + online softmax (warp-local) ==============
        #pragma unroll
        for (int t = 0; t < 16; t++) {
            float2 a2 = *(const float2*)&AMs[kv0 + t * 8 + (lane & 3) * 2];
            s[t * 4 + 0] += a2.x; s[t * 4 + 1] += a2.y;
            s[t * 4 + 2] += a2.x; s[t * 4 + 3] += a2.y;
        }
        if (j == qi) {
            const int wr0 = wrow + (lane >> 2), wr1 = wr0 + 8;
            #pragma unroll
            for (int t = 0; t < 16; t++) {
                int c0 = t * 8 + (lane & 3) * 2;
                if (c0     > wr0) s[t * 4 + 0] = -1e30f;
                if (c0 + 1 > wr0) s[t * 4 + 1] = -1e30f;
                if (c0     > wr1) s[t * 4 + 2] = -1e30f;
                if (c0 + 1 > wr1) s[t * 4 + 3] = -1e30f;
            }
        }
        float mx0 = -1e30f, mx1 = -1e30f;
        #pragma unroll
        for (int t = 0; t < 16; t++) {
            mx0 = fmaxf(mx0, fmaxf(s[t * 4 + 0], s[t * 4 + 1]));
            mx1 = fmaxf(mx1, fmaxf(s[t * 4 + 2], s[t * 4 + 3]));
        }
        mx0 = fmaxf(mx0, __shfl_xor_sync(0xffffffffu, mx0, 1));
        mx0 = fmaxf(mx0, __shfl_xor_sync(0xffffffffu, mx0, 2));
        mx1 = fmaxf(mx1, __shfl_xor_sync(0xffffffffu, mx1, 1));
        mx1 = fmaxf(mx1, __shfl_xor_sync(0xffffffffu, mx1, 2));
        const float mn0 = fmaxf(m0, mx0), mn1 = fmaxf(m1, mx1);
        const float corr0 = __expf(m0 - mn0), corr1 = __expf(m1 - mn1);

        uint32_t ph0[16], ph1[16], pl0[16], pl1[16];
        float ls0 = 0.f, ls1 = 0.f;
        #pragma unroll
        for (int t = 0; t < 16; t++) {
            float p0 = __expf(s[t * 4 + 0] - mn0);
            float p1 = __expf(s[t * 4 + 1] - mn0);
            float p2 = __expf(s[t * 4 + 2] - mn1);
            float p3 = __expf(s[t * 4 + 3] - mn1);
            ls0 += p0 + p1; ls1 += p2 + p3;
            float2 cx = *(const float2*)&CXs[kv0 + t * 8 + (lane & 3) * 2];
            p0 *= cx.x; p1 *= cx.y; p2 *= cx.x; p3 *= cx.y;
            __nv_bfloat16 h0 = __float2bfloat16(p0), h1 = __float2bfloat16(p1);
            __nv_bfloat16 h2 = __float2bfloat16(p2), h3 = __float2bfloat16(p3);
            ph0[t] = packbf(h0, h1);
            ph1[t] = packbf(h2, h3);
            pl0[t] = packbf(__float2bfloat16(p0 - __bfloat162float(h0)),
                            __float2bfloat16(p1 - __bfloat162float(h1)));
            pl1[t] = packbf(__float2bfloat16(p2 - __bfloat162float(h2)),
                            __float2bfloat16(p3 - __bfloat162float(h3)));
        }
        ls0 += __shfl_xor_sync(0xffffffffu, ls0, 1);
        ls0 += __shfl_xor_sync(0xffffffffu, ls0, 2);
        ls1 += __shfl_xor_sync(0xffffffffu, ls1, 1);
        ls1 += __shfl_xor_sync(0xffffffffu, ls1, 2);
        l0 = l0 * corr0 + ls0;  m0 = mn0;
        l1 = l1 * corr1 + ls1;  m1 = mn1;
        #pragma unroll
        for (int t = 0; t < 16; t++) {
            o[t * 4 + 0] *= corr0; o[t * 4 + 1] *= corr0;
            o[t * 4 + 2] *= corr1; o[t * 4 + 3] *= corr1;
        }

        // ================= O += P V (3 split passes fused) ==================
        #pragma unroll 1
        for (int ks = 0; ks < 8; ks++) {
            uint32_t afh[4] = {ph0[2 * ks], ph1[2 * ks], ph0[2 * ks + 1], ph1[2 * ks + 1]};
            uint32_t afl[4] = {pl0[2 * ks], pl1[2 * ks], pl0[2 * ks + 1], pl1[2 * ks + 1]};
            #pragma unroll
            for (int dp = 0; dp < 8; dp++) {
                uint32_t bvh[4], bvl[4];
                uint32_t bo = aoffBT + (uint32_t)(ks * 16 * ROWE) * 2 + dp * 32;
                ldsm4t(bvh, uVHI + bo);
                ldsm4t(bvl, uVLO + bo);
                mma16816(&o[(2 * dp) * 4],     afh, bvh);
                mma16816(&o[(2 * dp + 1) * 4], afh, bvh + 2);
                mma16816(&o[(2 * dp) * 4],     afh, bvl);
                mma16816(&o[(2 * dp + 1) * 4], afh, bvl + 2);
                mma16816(&o[(2 * dp) * 4],     afl, bvh);
                mma16816(&o[(2 * dp + 1) * 4], afl, bvh + 2);
            }
        }
    }

    // ================= epilogue =================
    const float hm = HM[h];
    const float sc0 = hm / l0, sc1 = hm / l1;
    const int gr0 = q0 + wrow + (lane >> 2);
    float* O0 = O + ((size_t)bh * Sc + gr0) * Dc;
    float* O1 = O0 + 8 * Dc;
    #pragma unroll
    for (int t = 0; t < 16; t++) {
        int c0 = t * 8 + (lane & 3) * 2;
        *(float2*)&O0[c0] = make_float2(o[t * 4 + 0] * sc0, o[t * 4 + 1] * sc0);
        *(float2*)&O1[c0] = make_float2(o[t * 4 + 2] * sc1, o[t * 4 + 3] * sc1);
    }
}

extern "C" void kernel_launch(void* const* d_in, const int* in_sizes, int n_in,
                              void* d_out, int out_size)
{
    const float* q   = (const float*)d_in[0];
    const float* k   = (const float*)d_in[1];
    const float* v   = (const float*)d_in[2];
    const float* am  = (const float*)d_in[3];
    const float* hm  = (const float*)d_in[4];
    const float* ctx = (const float*)d_in[5];
    float* out = (float*)d_out;

    convert_split<<<dim3(BHSD / (256 * 4), 3), 256>>>(q, k, v);

    cudaFuncSetAttribute(attn_hmma, cudaFuncAttributeMaxDynamicSharedMemorySize,
                         SMEM_BYTES);
    attn_hmma<<<512, NTH, SMEM_BYTES>>>(am, hm, ctx, out);
}

// round 5
// speedup vs baseline: 5.2503x; 1.4389x over previous
#include <cuda_runtime.h>
#include <cuda_fp16.h>
#include <cstdint>

// Shape: B=2, H=16, S=2048, D=128, fp32 in/out. GPT-Neo attention, no 1/sqrt(d).
constexpr int Sc = 2048, Dc = 128, NTH = 256;
constexpr int ROWE = 136;                   // half elems per padded smem row
constexpr int BHSD = 2 * 16 * 2048 * 128;   // 8388608

// Preconverted fp16 copies (device scratch; no runtime alloc).
__device__ __align__(16) __half g_qhi[BHSD];
__device__ __align__(16) __half g_qlo[BHSD];
__device__ __align__(16) __half g_khi[BHSD];
__device__ __align__(16) __half g_klo[BHSD];
__device__ __align__(16) __half g_vh [BHSD];

// ---- smem layout (bytes) ----
constexpr int OFF_AM  = 0;                  // float[2048]
constexpr int OFF_CX  = 8192;               // float[2048]
constexpr int OFF_QHI = 16384;              // 128 x ROWE halves
constexpr int TILEQ_B = 128 * ROWE * 2;     // 34816
constexpr int TILEK_B = 64 * ROWE * 2;      // 17408
constexpr int OFF_QLO = OFF_QHI + TILEQ_B;
constexpr int OFF_STG = OFF_QLO + TILEQ_B;  // 86016
constexpr int STG_B   = 3 * TILEK_B;        // KHI, KLO, VH = 52224
constexpr int SMEM_BYTES = OFF_STG + 2 * STG_B;   // 190464

__device__ __forceinline__ uint32_t smem_u32(const void* p) {
    uint32_t a;
    asm("{ .reg .u64 t; cvta.to.shared.u64 t, %1; cvt.u32.u64 %0, t; }"
        : "=r"(a) : "l"(p));
    return a;
}
__device__ __forceinline__ void cpa(uint32_t d, const void* s) {
    asm volatile("cp.async.cg.shared.global [%0], [%1], 16;" :: "r"(d), "l"(s));
}
#define CP_COMMIT() asm volatile("cp.async.commit_group;" ::: "memory")
#define CP_WAIT1()  asm volatile("cp.async.wait_group 1;" ::: "memory")

__device__ __forceinline__ void ldsm4(uint32_t* r, uint32_t a) {
    asm volatile("ldmatrix.sync.aligned.m8n8.x4.shared.b16 {%0,%1,%2,%3}, [%4];"
                 : "=r"(r[0]), "=r"(r[1]), "=r"(r[2]), "=r"(r[3]) : "r"(a));
}
__device__ __forceinline__ void ldsm4t(uint32_t* r, uint32_t a) {
    asm volatile("ldmatrix.sync.aligned.m8n8.x4.trans.shared.b16 {%0,%1,%2,%3}, [%4];"
                 : "=r"(r[0]), "=r"(r[1]), "=r"(r[2]), "=r"(r[3]) : "r"(a));
}
__device__ __forceinline__ void mma16816(float* d, const uint32_t* a, const uint32_t* b) {
    asm volatile("mma.sync.aligned.m16n8k16.row.col.f32.f16.f16.f32 "
                 "{%0,%1,%2,%3}, {%4,%5,%6,%7}, {%8,%9}, {%0,%1,%2,%3};"
                 : "+f"(d[0]), "+f"(d[1]), "+f"(d[2]), "+f"(d[3])
                 : "r"(a[0]), "r"(a[1]), "r"(a[2]), "r"(a[3]), "r"(b[0]), "r"(b[1]));
}
__device__ __forceinline__ uint32_t packh(__half a, __half b) {
    __half2 v(a, b);   // a -> low 16 bits
    return *(uint32_t*)&v;
}

// ---- preconvert: fp32 -> fp16 hi/lo (Q,K) and fp16 (V). Pure BW. ----
__global__ __launch_bounds__(256)
void convert_split(const float* __restrict__ Q, const float* __restrict__ K,
                   const float* __restrict__ V)
{
    int i = (blockIdx.x * 256 + threadIdx.x) * 4;
    if (blockIdx.y == 2) {
        float4 x = *(const float4*)(V + i);
        *(uint2*)&g_vh[i] = make_uint2(
            packh(__float2half(x.x), __float2half(x.y)),
            packh(__float2half(x.z), __float2half(x.w)));
        return;
    }
    const float* src = (blockIdx.y == 0) ? Q : K;
    __half* hi = (blockIdx.y == 0) ? g_qhi : g_khi;
    __half* lo = (blockIdx.y == 0) ? g_qlo : g_klo;
    float4 x = *(const float4*)(src + i);
    __half h0 = __float2half(x.x), h1 = __float2half(x.y);
    __half h2 = __float2half(x.z), h3 = __float2half(x.w);
    *(uint2*)&hi[i] = make_uint2(packh(h0, h1), packh(h2, h3));
    *(uint2*)&lo[i] = make_uint2(
        packh(__float2half(x.x - __half2float(h0)), __float2half(x.y - __half2float(h1))),
        packh(__float2half(x.z - __half2float(h2)), __float2half(x.w - __half2float(h3))));
}

// stage one 64-row KV group (K hi/lo + V) via cp.async
__device__ __forceinline__ void stage_kv(uint32_t dst, int bh, int kv0, int tid) {
    const char* gkh = (const char*)(g_khi + ((size_t)bh * Sc + kv0) * Dc);
    const char* gkl = (const char*)(g_klo + ((size_t)bh * Sc + kv0) * Dc);
    const char* gvh = (const char*)(g_vh  + ((size_t)bh * Sc + kv0) * Dc);
    #pragma unroll
    for (int i2 = 0; i2 < 4; i2++) {
        int id = tid + 256 * i2;               // 0..1023
        int r = id >> 4, c = id & 15;
        uint32_t so = (uint32_t)(r * (ROWE * 2) + c * 16);
        uint32_t go = (uint32_t)(r * 256 + c * 16);
        cpa(dst + so, gkh + go);
        cpa(dst + TILEK_B + so, gkl + go);
        cpa(dst + 2 * TILEK_B + so, gvh + go);
    }
}

__global__ __launch_bounds__(NTH, 1)
void attn_hmma(const float* __restrict__ AM, const float* __restrict__ HM,
               const float* __restrict__ CTX, float* __restrict__ O)
{
    extern __shared__ char sm[];
    float* AMs = (float*)(sm + OFF_AM);
    float* CXs = (float*)(sm + OFF_CX);
    const uint32_t sb = smem_u32(sm);
    const uint32_t uQHI = sb + OFF_QHI, uQLO = sb + OFF_QLO;

    const int tid = threadIdx.x, lane = tid & 31, warp = tid >> 5;
    const int wrow = warp * 16;
    const int bx = blockIdx.x;
    const int qi = (Sc / 128 - 1) - (bx >> 5);      // LPT: heavy CTAs first
    const int bh = bx & 31, b = bh >> 4, h = bh & 15;
    const int q0 = qi * 128;
    const int NS = 2 * (qi + 1);                    // 64-col kv steps

    // ldmatrix lane->address offsets (bytes)
    const uint32_t aoffA = (uint32_t)((wrow + (lane & 15)) * ROWE + (lane >> 4) * 8) * 2;
    const uint32_t aoffB = (uint32_t)(((lane & 7) + ((lane >> 4) << 3)) * ROWE
                                      + (((lane >> 3) & 1) << 3)) * 2;
    const uint32_t aoffBT = (uint32_t)(((lane & 7) + (((lane >> 3) & 1) << 3)) * ROWE
                                       + ((lane >> 4) << 3)) * 2;

    float o[64];
    #pragma unroll
    for (int i = 0; i < 64; i++) o[i] = 0.f;
    float m0 = -1e30f, m1 = -1e30f, l0 = 0.f, l1 = 0.f;

    // ---- prologue group 0: AM/CX + Q hi/lo + KV stage 0 ----
    #pragma unroll
    for (int i2 = 0; i2 < 4; i2++) {
        int id = tid + 256 * i2;                    // 0..1023
        if (id < 512) cpa(sb + OFF_AM + id * 16, (const char*)(AM + b * Sc) + id * 16);
        else cpa(sb + OFF_CX + (id - 512) * 16,
                 (const char*)(CTX + b * Sc) + (id - 512) * 16);
    }
    {
        const char* gqh = (const char*)(g_qhi + ((size_t)bh * Sc + q0) * Dc);
        const char* gql = (const char*)(g_qlo + ((size_t)bh * Sc + q0) * Dc);
        #pragma unroll
        for (int i2 = 0; i2 < 8; i2++) {
            int id = tid + 256 * i2;                // 0..2047
            int r = id >> 4, c = id & 15;
            uint32_t so = (uint32_t)(r * (ROWE * 2) + c * 16);
            uint32_t go = (uint32_t)(r * 256 + c * 16);
            cpa(uQHI + so, gqh + go);
            cpa(uQLO + so, gql + go);
        }
    }
    stage_kv(sb + OFF_STG, bh, 0, tid);
    CP_COMMIT();
    // prologue group 1: KV stage 1
    if (NS > 1) stage_kv(sb + OFF_STG + STG_B, bh, 64, tid);
    CP_COMMIT();

    for (int js = 0; js < NS; js++) {
        const int kv0 = js * 64;
        CP_WAIT1();                 // stage js landed (js+1 may still fly)
        __syncthreads();

        const uint32_t bKHI = sb + OFF_STG + (js & 1) * STG_B;
        const uint32_t bKLO = bKHI + TILEK_B;
        const uint32_t bVH  = bKHI + 2 * TILEK_B;

        // ================= S = Q K^T (3 fp16 split passes) =================
        float s[32];
        #pragma unroll
        for (int i = 0; i < 32; i++) s[i] = 0.f;

        #pragma unroll 1
        for (int ks = 0; ks < 8; ks++) {
            uint32_t ah[4], al[4];
            ldsm4(ah, uQHI + aoffA + ks * 32);
            ldsm4(al, uQLO + aoffA + ks * 32);
            #pragma unroll
            for (int np = 0; np < 4; np++) {
                uint32_t bh4[4], bl4[4];
                uint32_t bo = aoffB + (uint32_t)(np * 16 * ROWE) * 2 + ks * 32;
                ldsm4(bh4, bKHI + bo);
                ldsm4(bl4, bKLO + bo);
                mma16816(&s[(2 * np) * 4],     ah, bh4);
                mma16816(&s[(2 * np + 1) * 4], ah, bh4 + 2);
                mma16816(&s[(2 * np) * 4],     ah, bl4);
                mma16816(&s[(2 * np + 1) * 4], ah, bl4 + 2);
                mma16816(&s[(2 * np) * 4],     al, bh4);
                mma16816(&s[(2 * np + 1) * 4], al, bh4 + 2);
            }
        }

        // ================= masks + online softmax ==============
        #pragma unroll
        for (int t = 0; t < 8; t++) {
            float2 a2 = *(const float2*)&AMs[kv0 + t * 8 + (lane & 3) * 2];
            s[t * 4 + 0] += a2.x; s[t * 4 + 1] += a2.y;
            s[t * 4 + 2] += a2.x; s[t * 4 + 3] += a2.y;
        }
        if (js >= 2 * qi) {         // diagonal region
            const int off = kv0 - q0;
            const int wr0 = wrow + (lane >> 2), wr1 = wr0 + 8;
            #pragma unroll
            for (int t = 0; t < 8; t++) {
                int c0 = off + t * 8 + (lane & 3) * 2;
                if (c0     > wr0) s[t * 4 + 0] = -1e30f;
                if (c0 + 1 > wr0) s[t * 4 + 1] = -1e30f;
                if (c0     > wr1) s[t * 4 + 2] = -1e30f;
                if (c0 + 1 > wr1) s[t * 4 + 3] = -1e30f;
            }
        }
        float mx0 = -1e30f, mx1 = -1e30f;
        #pragma unroll
        for (int t = 0; t < 8; t++) {
            mx0 = fmaxf(mx0, fmaxf(s[t * 4 + 0], s[t * 4 + 1]));
            mx1 = fmaxf(mx1, fmaxf(s[t * 4 + 2], s[t * 4 + 3]));
        }
        mx0 = fmaxf(mx0, __shfl_xor_sync(0xffffffffu, mx0, 1));
        mx0 = fmaxf(mx0, __shfl_xor_sync(0xffffffffu, mx0, 2));
        mx1 = fmaxf(mx1, __shfl_xor_sync(0xffffffffu, mx1, 1));
        mx1 = fmaxf(mx1, __shfl_xor_sync(0xffffffffu, mx1, 2));
        const float mn0 = fmaxf(m0, mx0), mn1 = fmaxf(m1, mx1);
        const float corr0 = __expf(m0 - mn0), corr1 = __expf(m1 - mn1);

        uint32_t ph0[8], ph1[8];
        float ls0 = 0.f, ls1 = 0.f;
        #pragma unroll
        for (int t = 0; t < 8; t++) {
            float p0 = __expf(s[t * 4 + 0] - mn0);
            float p1 = __expf(s[t * 4 + 1] - mn0);
            float p2 = __expf(s[t * 4 + 2] - mn1);
            float p3 = __expf(s[t * 4 + 3] - mn1);
            ls0 += p0 + p1; ls1 += p2 + p3;
            float2 cx = *(const float2*)&CXs[kv0 + t * 8 + (lane & 3) * 2];
            ph0[t] = packh(__float2half(p0 * cx.x), __float2half(p1 * cx.y));
            ph1[t] = packh(__float2half(p2 * cx.x), __float2half(p3 * cx.y));
        }
        ls0 += __shfl_xor_sync(0xffffffffu, ls0, 1);
        ls0 += __shfl_xor_sync(0xffffffffu, ls0, 2);
        ls1 += __shfl_xor_sync(0xffffffffu, ls1, 1);
        ls1 += __shfl_xor_sync(0xffffffffu, ls1, 2);
        l0 = l0 * corr0 + ls0;  m0 = mn0;
        l1 = l1 * corr1 + ls1;  m1 = mn1;
        #pragma unroll
        for (int t = 0; t < 16; t++) {
            o[t * 4 + 0] *= corr0; o[t * 4 + 1] *= corr0;
            o[t * 4 + 2] *= corr1; o[t * 4 + 3] *= corr1;
        }

        // ================= O += P V (single fp16 pass) ==================
        #pragma unroll 1
        for (int ks = 0; ks < 4; ks++) {
            uint32_t af[4] = {ph0[2 * ks], ph1[2 * ks], ph0[2 * ks + 1], ph1[2 * ks + 1]};
            #pragma unroll
            for (int dp = 0; dp < 8; dp++) {
                uint32_t bv[4];
                uint32_t bo = aoffBT + (uint32_t)(ks * 16 * ROWE) * 2 + dp * 32;
                ldsm4t(bv, bVH + bo);
                mma16816(&o[(2 * dp) * 4],     af, bv);
                mma16816(&o[(2 * dp + 1) * 4], af, bv + 2);
            }
        }

        __syncthreads();            // all warps done with buf (js&1)
        if (js + 2 < NS) stage_kv(sb + OFF_STG + (js & 1) * STG_B, bh, kv0 + 128, tid);
        CP_COMMIT();                // one group per iteration (may be empty)
    }

    // ================= epilogue =================
    const float hm = HM[h];
    const float sc0 = hm / l0, sc1 = hm / l1;
    const int gr0 = q0 + wrow + (lane >> 2);
    float* O0 = O + ((size_t)bh * Sc + gr0) * Dc;
    float* O1 = O0 + 8 * Dc;
    #pragma unroll
    for (int t = 0; t < 16; t++) {
        int c0 = t * 8 + (lane & 3) * 2;
        *(float2*)&O0[c0] = make_float2(o[t * 4 + 0] * sc0, o[t * 4 + 1] * sc0);
        *(float2*)&O1[c0] = make_float2(o[t * 4 + 2] * sc1, o[t * 4 + 3] * sc1);
    }
}

extern "C" void kernel_launch(void* const* d_in, const int* in_sizes, int n_in,
                              void* d_out, int out_size)
{
    const float* q   = (const float*)d_in[0];
    const float* k   = (const float*)d_in[1];
    const float* v   = (const float*)d_in[2];
    const float* am  = (const float*)d_in[3];
    const float* hm  = (const float*)d_in[4];
    const float* ctx = (const float*)d_in[5];
    float* out = (float*)d_out;

    convert_split<<<dim3(BHSD / (256 * 4), 3), 256>>>(q, k, v);

    cudaFuncSetAttribute(attn_hmma, cudaFuncAttributeMaxDynamicSharedMemorySize,
                         SMEM_BYTES);
    attn_hmma<<<512, NTH, SMEM_BYTES>>>(am, hm, ctx, out);
}

// round 6
// speedup vs baseline: 5.8600x; 1.1161x over previous
#include <cuda_runtime.h>
#include <cuda_fp16.h>
#include <cstdint>

// Shape: B=2, H=16, S=2048, D=128, fp32 in/out. GPT-Neo attention, no 1/sqrt(d).
constexpr int Sc = 2048, Dc = 128, NTH = 256;
constexpr int ROWE = 136;                   // half elems per padded smem row
constexpr int BHSD = 2 * 16 * 2048 * 128;   // 8388608

// Preconverted fp16 copies (device scratch; no runtime alloc).
__device__ __align__(16) __half g_qhi[BHSD];
__device__ __align__(16) __half g_qlo[BHSD];
__device__ __align__(16) __half g_khi[BHSD];
__device__ __align__(16) __half g_klo[BHSD];
__device__ __align__(16) __half g_vh [BHSD];

// ---- smem layout (bytes): Q hi/lo + 3-stage KV ring ----
constexpr int TILEQ_B = 128 * ROWE * 2;     // 34816
constexpr int TILEK_B = 64 * ROWE * 2;      // 17408
constexpr int OFF_QHI = 0;
constexpr int OFF_QLO = TILEQ_B;
constexpr int OFF_STG = 2 * TILEQ_B;        // 69632
constexpr int STG_B   = 3 * TILEK_B;        // KHI, KLO, VH = 52224
constexpr int SMEM_BYTES = OFF_STG + 3 * STG_B;   // 226304 (<= 227KB)

__device__ __forceinline__ uint32_t smem_u32(const void* p) {
    uint32_t a;
    asm("{ .reg .u64 t; cvta.to.shared.u64 t, %1; cvt.u32.u64 %0, t; }"
        : "=r"(a) : "l"(p));
    return a;
}
__device__ __forceinline__ void cpa(uint32_t d, const void* s) {
    asm volatile("cp.async.cg.shared.global [%0], [%1], 16;" :: "r"(d), "l"(s));
}
#define CP_COMMIT() asm volatile("cp.async.commit_group;" ::: "memory")
#define CP_WAIT1()  asm volatile("cp.async.wait_group 1;" ::: "memory")

__device__ __forceinline__ void ldsm4(uint32_t* r, uint32_t a) {
    asm volatile("ldmatrix.sync.aligned.m8n8.x4.shared.b16 {%0,%1,%2,%3}, [%4];"
                 : "=r"(r[0]), "=r"(r[1]), "=r"(r[2]), "=r"(r[3]) : "r"(a));
}
__device__ __forceinline__ void ldsm4t(uint32_t* r, uint32_t a) {
    asm volatile("ldmatrix.sync.aligned.m8n8.x4.trans.shared.b16 {%0,%1,%2,%3}, [%4];"
                 : "=r"(r[0]), "=r"(r[1]), "=r"(r[2]), "=r"(r[3]) : "r"(a));
}
__device__ __forceinline__ void mma16816(float* d, const uint32_t* a, const uint32_t* b) {
    asm volatile("mma.sync.aligned.m16n8k16.row.col.f32.f16.f16.f32 "
                 "{%0,%1,%2,%3}, {%4,%5,%6,%7}, {%8,%9}, {%0,%1,%2,%3};"
                 : "+f"(d[0]), "+f"(d[1]), "+f"(d[2]), "+f"(d[3])
                 : "r"(a[0]), "r"(a[1]), "r"(a[2]), "r"(a[3]), "r"(b[0]), "r"(b[1]));
}
__device__ __forceinline__ uint32_t packh(__half a, __half b) {
    __half2 v(a, b);
    return *(uint32_t*)&v;
}

// ---- preconvert: fp32 -> fp16 hi/lo (Q,K) and fp16 (V). Pure BW. ----
__global__ __launch_bounds__(256)
void convert_split(const float* __restrict__ Q, const float* __restrict__ K,
                   const float* __restrict__ V)
{
    int i = (blockIdx.x * 256 + threadIdx.x) * 4;
    if (blockIdx.y == 2) {
        float4 x = *(const float4*)(V + i);
        *(uint2*)&g_vh[i] = make_uint2(
            packh(__float2half(x.x), __float2half(x.y)),
            packh(__float2half(x.z), __float2half(x.w)));
        return;
    }
    const float* src = (blockIdx.y == 0) ? Q : K;
    __half* hi = (blockIdx.y == 0) ? g_qhi : g_khi;
    __half* lo = (blockIdx.y == 0) ? g_qlo : g_klo;
    float4 x = *(const float4*)(src + i);
    __half h0 = __float2half(x.x), h1 = __float2half(x.y);
    __half h2 = __float2half(x.z), h3 = __float2half(x.w);
    *(uint2*)&hi[i] = make_uint2(packh(h0, h1), packh(h2, h3));
    *(uint2*)&lo[i] = make_uint2(
        packh(__float2half(x.x - __half2float(h0)), __float2half(x.y - __half2float(h1))),
        packh(__float2half(x.z - __half2float(h2)), __float2half(x.w - __half2float(h3))));
}

// stage one 64-row KV group (K hi/lo + V) via cp.async
__device__ __forceinline__ void stage_kv(uint32_t dst, int bh, int kv0, int tid) {
    const char* gkh = (const char*)(g_khi + ((size_t)bh * Sc + kv0) * Dc);
    const char* gkl = (const char*)(g_klo + ((size_t)bh * Sc + kv0) * Dc);
    const char* gvh = (const char*)(g_vh  + ((size_t)bh * Sc + kv0) * Dc);
    #pragma unroll
    for (int i2 = 0; i2 < 4; i2++) {
        int id = tid + 256 * i2;               // 0..1023
        int r = id >> 4, c = id & 15;
        uint32_t so = (uint32_t)(r * (ROWE * 2) + c * 16);
        uint32_t go = (uint32_t)(r * 256 + c * 16);
        cpa(dst + so, gkh + go);
        cpa(dst + TILEK_B + so, gkl + go);
        cpa(dst + 2 * TILEK_B + so, gvh + go);
    }
}

__global__ __launch_bounds__(NTH, 1)
void attn_hmma(const float* __restrict__ AM, const float* __restrict__ HM,
               const float* __restrict__ CTX, float* __restrict__ O)
{
    extern __shared__ char sm[];
    const uint32_t sb = smem_u32(sm);
    const uint32_t uQHI = sb + OFF_QHI, uQLO = sb + OFF_QLO;

    const int tid = threadIdx.x, lane = tid & 31, warp = tid >> 5;
    const int wrow = warp * 16;
    const int bx = blockIdx.x;
    const int qi = (Sc / 128 - 1) - (bx >> 5);      // LPT: heavy CTAs first
    const int bh = bx & 31, b = bh >> 4, h = bh & 15;
    const int q0 = qi * 128;
    const int NS = 2 * (qi + 1);                    // 64-col kv steps

    // ldmatrix lane->address offsets (bytes)
    const uint32_t aoffA = (uint32_t)((wrow + (lane & 15)) * ROWE + (lane >> 4) * 8) * 2;
    const uint32_t aoffB = (uint32_t)(((lane & 7) + ((lane >> 4) << 3)) * ROWE
                                      + (((lane >> 3) & 1) << 3)) * 2;
    const uint32_t aoffBT = (uint32_t)(((lane & 7) + (((lane >> 3) & 1) << 3)) * ROWE
                                       + ((lane >> 4) << 3)) * 2;

    float o[64];
    #pragma unroll
    for (int i = 0; i < 64; i++) o[i] = 0.f;
    float m0 = -1e30f, m1 = -1e30f, l0 = 0.f, l1 = 0.f;

    // ---- prologue: group0 = Q + KV0; group1 = KV1 ----
    {
        const char* gqh = (const char*)(g_qhi + ((size_t)bh * Sc + q0) * Dc);
        const char* gql = (const char*)(g_qlo + ((size_t)bh * Sc + q0) * Dc);
        #pragma unroll
        for (int i2 = 0; i2 < 8; i2++) {
            int id = tid + 256 * i2;                // 0..2047
            int r = id >> 4, c = id & 15;
            uint32_t so = (uint32_t)(r * (ROWE * 2) + c * 16);
            uint32_t go = (uint32_t)(r * 256 + c * 16);
            cpa(uQHI + so, gqh + go);
            cpa(uQLO + so, gql + go);
        }
    }
    stage_kv(sb + OFF_STG, bh, 0, tid);
    CP_COMMIT();
    if (NS > 1) stage_kv(sb + OFF_STG + STG_B, bh, 64, tid);
    CP_COMMIT();

    // ---- load loop-invariant Q fragments into registers ----
    CP_WAIT1();                 // group0 (Q + KV0) landed
    __syncthreads();
    uint32_t qfh[32], qfl[32];
    #pragma unroll
    for (int ks = 0; ks < 8; ks++) {
        ldsm4(&qfh[ks * 4], uQHI + aoffA + ks * 32);
        ldsm4(&qfl[ks * 4], uQLO + aoffA + ks * 32);
    }

    const float2* AMp = (const float2*)(AM + (size_t)b * Sc);
    const float2* CXp = (const float2*)(CTX + (size_t)b * Sc);

    for (int js = 0; js < NS; js++) {
        const int kv0 = js * 64;
        CP_WAIT1();             // stage js landed (js+1 may still fly)
        __syncthreads();        // all warps past js-1 -> ring slot (js+2)%3 free
        if (js + 2 < NS) stage_kv(sb + OFF_STG + ((js + 2) % 3) * STG_B,
                                  bh, kv0 + 128, tid);
        CP_COMMIT();

        const uint32_t bKHI = sb + OFF_STG + (js % 3) * STG_B;
        const uint32_t bKLO = bKHI + TILEK_B;
        const uint32_t bVH  = bKHI + 2 * TILEK_B;

        // ========== S = Q K^T (3 fp16 split passes, np-paired) ==========
        float s[32];
        #pragma unroll
        for (int i = 0; i < 32; i++) s[i] = 0.f;

        #pragma unroll
        for (int ks = 0; ks < 8; ks++) {
            const uint32_t* ah = &qfh[ks * 4];
            const uint32_t* al = &qfl[ks * 4];
            #pragma unroll
            for (int pp = 0; pp < 2; pp++) {
                uint32_t b0h[4], b0l[4], b1h[4], b1l[4];
                uint32_t bo0 = aoffB + (uint32_t)((2 * pp) * 16 * ROWE) * 2 + ks * 32;
                uint32_t bo1 = bo0 + (uint32_t)(16 * ROWE) * 2;
                ldsm4(b0h, bKHI + bo0);
                ldsm4(b1h, bKHI + bo1);
                ldsm4(b0l, bKLO + bo0);
                ldsm4(b1l, bKLO + bo1);
                float* s0 = &s[(4 * pp) * 4];
                float* s1 = &s[(4 * pp + 1) * 4];
                float* s2 = &s[(4 * pp + 2) * 4];
                float* s3 = &s[(4 * pp + 3) * 4];
                mma16816(s0, ah, b0h);  mma16816(s1, ah, b0h + 2);
                mma16816(s2, ah, b1h);  mma16816(s3, ah, b1h + 2);
                mma16816(s0, ah, b0l);  mma16816(s1, ah, b0l + 2);
                mma16816(s2, ah, b1l);  mma16816(s3, ah, b1l + 2);
                mma16816(s0, al, b0h);  mma16816(s1, al, b0h + 2);
                mma16816(s2, al, b1h);  mma16816(s3, al, b1h + 2);
            }
        }

        // ========== masks + online softmax (warp-local) ==========
        #pragma unroll
        for (int t = 0; t < 8; t++) {
            float2 a2 = __ldg(&AMp[kv0 / 2 + t * 4 + (lane & 3)]);
            s[t * 4 + 0] += a2.x; s[t * 4 + 1] += a2.y;
            s[t * 4 + 2] += a2.x; s[t * 4 + 3] += a2.y;
        }
        if (js >= 2 * qi) {         // diagonal region
            const int off = kv0 - q0;
            const int wr0 = wrow + (lane >> 2), wr1 = wr0 + 8;
            #pragma unroll
            for (int t = 0; t < 8; t++) {
                int c0 = off + t * 8 + (lane & 3) * 2;
                if (c0     > wr0) s[t * 4 + 0] = -1e30f;
                if (c0 + 1 > wr0) s[t * 4 + 1] = -1e30f;
                if (c0     > wr1) s[t * 4 + 2] = -1e30f;
                if (c0 + 1 > wr1) s[t * 4 + 3] = -1e30f;
            }
        }
        float mx0 = -1e30f, mx1 = -1e30f;
        #pragma unroll
        for (int t = 0; t < 8; t++) {
            mx0 = fmaxf(mx0, fmaxf(s[t * 4 + 0], s[t * 4 + 1]));
            mx1 = fmaxf(mx1, fmaxf(s[t * 4 + 2], s[t * 4 + 3]));
        }
        mx0 = fmaxf(mx0, __shfl_xor_sync(0xffffffffu, mx0, 1));
        mx0 = fmaxf(mx0, __shfl_xor_sync(0xffffffffu, mx0, 2));
        mx1 = fmaxf(mx1, __shfl_xor_sync(0xffffffffu, mx1, 1));
        mx1 = fmaxf(mx1, __shfl_xor_sync(0xffffffffu, mx1, 2));
        const float mn0 = fmaxf(m0, mx0), mn1 = fmaxf(m1, mx1);
        const float corr0 = __expf(m0 - mn0), corr1 = __expf(m1 - mn1);

        uint32_t ph0[8], ph1[8];
        float ls0 = 0.f, ls1 = 0.f;
        #pragma unroll
        for (int t = 0; t < 8; t++) {
            float p0 = __expf(s[t * 4 + 0] - mn0);
            float p1 = __expf(s[t * 4 + 1] - mn0);
            float p2 = __expf(s[t * 4 + 2] - mn1);
            float p3 = __expf(s[t * 4 + 3] - mn1);
            ls0 += p0 + p1; ls1 += p2 + p3;
            float2 cx = __ldg(&CXp[kv0 / 2 + t * 4 + (lane & 3)]);
            ph0[t] = packh(__float2half(p0 * cx.x), __float2half(p1 * cx.y));
            ph1[t] = packh(__float2half(p2 * cx.x), __float2half(p3 * cx.y));
        }
        ls0 += __shfl_xor_sync(0xffffffffu, ls0, 1);
        ls0 += __shfl_xor_sync(0xffffffffu, ls0, 2);
        ls1 += __shfl_xor_sync(0xffffffffu, ls1, 1);
        ls1 += __shfl_xor_sync(0xffffffffu, ls1, 2);
        l0 = l0 * corr0 + ls0;  m0 = mn0;
        l1 = l1 * corr1 + ls1;  m1 = mn1;
        #pragma unroll
        for (int t = 0; t < 16; t++) {
            o[t * 4 + 0] *= corr0; o[t * 4 + 1] *= corr0;
            o[t * 4 + 2] *= corr1; o[t * 4 + 3] *= corr1;
        }

        // ========== O += P V (single fp16 pass) ==========
        #pragma unroll
        for (int ks = 0; ks < 4; ks++) {
            uint32_t af[4] = {ph0[2 * ks], ph1[2 * ks], ph0[2 * ks + 1], ph1[2 * ks + 1]};
            #pragma unroll
            for (int dp = 0; dp < 8; dp++) {
                uint32_t bv[4];
                uint32_t bo = aoffBT + (uint32_t)(ks * 16 * ROWE) * 2 + dp * 32;
                ldsm4t(bv, bVH + bo);
                mma16816(&o[(2 * dp) * 4],     af, bv);
                mma16816(&o[(2 * dp + 1) * 4], af, bv + 2);
            }
        }
    }

    // ================= epilogue =================
    const float hm = __ldg(&HM[h]);
    const float sc0 = hm / l0, sc1 = hm / l1;
    const int gr0 = q0 + wrow + (lane >> 2);
    float* O0 = O + ((size_t)bh * Sc + gr0) * Dc;
    float* O1 = O0 + 8 * Dc;
    #pragma unroll
    for (int t = 0; t < 16; t++) {
        int c0 = t * 8 + (lane & 3) * 2;
        *(float2*)&O0[c0] = make_float2(o[t * 4 + 0] * sc0, o[t * 4 + 1] * sc0);
        *(float2*)&O1[c0] = make_float2(o[t * 4 + 2] * sc1, o[t * 4 + 3] * sc1);
    }
}

extern "C" void kernel_launch(void* const* d_in, const int* in_sizes, int n_in,
                              void* d_out, int out_size)
{
    const float* q   = (const float*)d_in[0];
    const float* k   = (const float*)d_in[1];
    const float* v   = (const float*)d_in[2];
    const float* am  = (const float*)d_in[3];
    const float* hm  = (const float*)d_in[4];
    const float* ctx = (const float*)d_in[5];
    float* out = (float*)d_out;

    convert_split<<<dim3(BHSD / (256 * 4), 3), 256>>>(q, k, v);

    cudaFuncSetAttribute(attn_hmma, cudaFuncAttributeMaxDynamicSharedMemorySize,
                         SMEM_BYTES);
    attn_hmma<<<512, NTH, SMEM_BYTES>>>(am, hm, ctx, out);
}